// round 14
// baseline (speedup 1.0000x reference)
#include <cuda_runtime.h>

#define BQ 128
#define SQ 512
#define NQ 10
#define NST 1024
#define TPB 256
#define AMPS 4
#define PI_F 3.14159265358979f

typedef unsigned long long u64;

// scratch (no allocations allowed)
__device__ float g_dta[BQ*SQ*NQ];
__device__ float g_C[BQ*SQ*NQ];

__device__ __forceinline__ float2 cmul(float2 a, float2 b){
  return make_float2(a.x*b.x - a.y*b.y, a.x*b.y + a.y*b.x);
}

// ---- packed f32x2 helpers (Blackwell FFMA2 via PTX); carrier = u64 ----------
__device__ __forceinline__ u64 pk2(float x, float y){
  u64 d; asm("mov.b64 %0,{%1,%2};" : "=l"(d) : "f"(x), "f"(y)); return d;
}
__device__ __forceinline__ float2 up2(u64 d){
  float2 f; asm("mov.b64 {%0,%1},%2;" : "=f"(f.x), "=f"(f.y) : "l"(d)); return f;
}
__device__ __forceinline__ u64 fma2d(u64 a, u64 b, u64 c){
  u64 r; asm("fma.rn.f32x2 %0,%1,%2,%3;" : "=l"(r) : "l"(a), "l"(b), "l"(c)); return r;
}
__device__ __forceinline__ u64 mul2d(u64 a, u64 b){
  u64 r; asm("mul.rn.f32x2 %0,%1,%2;" : "=l"(r) : "l"(a), "l"(b)); return r;
}
__device__ __forceinline__ u64 fixPQ(u64 P, u64 Q){
  float2 p = up2(P), q = up2(Q);
  return pk2(p.x - q.y, p.y + q.x);
}

// verified QSVT gather map
__device__ __forceinline__ int gmap(int a){
  int v = a;
  v ^= (v & 1) << 9;
#pragma unroll
  for (int i = 8; i >= 0; --i) v ^= ((v >> (9-i)) & 1) << (8-i);
  return v;
}

// bit transpose: swap amp bits 9<->1, 8<->0, 7<->2 (involution)
__device__ __forceinline__ int bswap(int x){
  int keep = x & 0x78;
  int b9=(x>>9)&1, b8=(x>>8)&1, b7=(x>>7)&1;
  int b2=(x>>2)&1, b1=(x>>1)&1, b0=x&1;
  return keep | (b1<<9) | (b0<<8) | (b2<<7) | (b7<<2) | (b9<<1) | b8;
}
// inverse of chain gather g(x)=x^(x>>1)
__device__ __forceinline__ int grayinv(int j){
  int x = 0, c = 0;
#pragma unroll
  for (int p = 9; p >= 0; --p){ c ^= (j>>p)&1; x |= c<<p; }
  return x;
}

// ---------------------------------------------------------------------------
__global__ void prep_kernel(const float* __restrict__ angles,
                            const float* __restrict__ W_x,
                            const float* __restrict__ W_dt,
                            const float* __restrict__ b_dt)
{
  int idx = blockIdx.x*blockDim.x + threadIdx.x;
  if (idx >= BQ*SQ) return;
  float a[NQ];
#pragma unroll
  for (int n=0;n<NQ;n++) a[n] = angles[idx*NQ + n];
  float dtr[5];
#pragma unroll
  for (int r=0;r<5;r++){
    float s = 0.f;
#pragma unroll
    for (int n=0;n<NQ;n++) s += a[n]*W_x[r*NQ+n];
    dtr[r]=s;
  }
#pragma unroll
  for (int k=0;k<NQ;k++){
    float s=0.f;
#pragma unroll
    for (int n=0;n<NQ;n++) s += a[n]*W_x[(15+k)*NQ+n];
    g_C[idx*NQ+k]=s;
  }
#pragma unroll
  for (int n=0;n<NQ;n++){
    float s = b_dt[n];
#pragma unroll
    for (int r=0;r<5;r++) s += dtr[r]*W_dt[n*5+r];
    float sp = fmaxf(s, 0.f) + log1pf(expf(-fabsf(s)));
    g_dta[idx*NQ+n] = tanhf(sp)*PI_F;
  }
}

// complex shuffle gate on lane bit q, register-resident coefficients
__device__ __forceinline__ void shflCr(u64* v, const u64* Cq, int q){
  u64 csx=Cq[0], csy=Cq[1], cpx=Cq[2], cpy=Cq[3];
#pragma unroll
  for (int m=0;m<AMPS;m++){
    u64 p = __shfl_xor_sync(0xffffffffu, v[m], 1<<q);
    u64 P = fma2d(cpx, p, mul2d(csx, v[m]));
    u64 Q = fma2d(cpy, p, mul2d(csy, v[m]));
    v[m] = fixPQ(P, Q);
  }
}

// real (RY) shuffle gate on lane bit q
__device__ __forceinline__ void shflRp(u64* v, float c, float s, int q, int lane){
  float sp = ((lane >> q) & 1) ? s : -s;
  u64 c2 = pk2(c, c), sp2 = pk2(sp, sp);
#pragma unroll
  for (int m=0;m<AMPS;m++){
    u64 p = __shfl_xor_sync(0xffffffffu, v[m], 1<<q);
    v[m] = fma2d(sp2, p, mul2d(c2, v[m]));
  }
}

// complex register gate on m-bit bm (shared coefficients)
__device__ __forceinline__ void regCp(u64* v, const u64* G, int bm){
  u64 g0x=G[0],g0y=G[1],g1x=G[2],g1y=G[3],g2x=G[4],g2y=G[5],g3x=G[6],g3y=G[7];
#pragma unroll
  for (int m=0;m<AMPS;m++){
    if (m & bm) continue;
    int mh = m | bm;
    u64 lo = v[m], hi = v[mh];
    u64 P = fma2d(g1x, hi, mul2d(g0x, lo));
    u64 Q = fma2d(g1y, hi, mul2d(g0y, lo));
    v[m]  = fixPQ(P, Q);
    P = fma2d(g3x, hi, mul2d(g2x, lo));
    Q = fma2d(g3y, hi, mul2d(g2y, lo));
    v[mh] = fixPQ(P, Q);
  }
}

// real register gate on m-bit bm
__device__ __forceinline__ void regRp(u64* v, float c, float s, int bm){
  u64 c2 = pk2(c,c), s2 = pk2(s,s), ns2 = pk2(-s,-s);
#pragma unroll
  for (int m=0;m<AMPS;m++){
    if (m & bm) continue;
    int mh = m | bm;
    u64 lo = v[m], hi = v[mh];
    v[m]  = fma2d(ns2, hi, mul2d(c2, lo));
    v[mh] = fma2d(c2, hi, mul2d(s2, lo));
  }
}

// ---------------------------------------------------------------------------
// R12 transpose-exchange structure + R13 register-hoisted shuffle coeffs +
// R14: cross-step pipelined phase factors. vE[m] = e^{i phi} for the CURRENT
// step is computed during the PREVIOUS step (phase depends only on dt, which
// is prefetched); init head shrinks to am * vE. S-tables are intra-step
// scratch: whsN published at step top (T1 bar orders), tables built in phase C
// slack (T2 bar orders), vE recomputed in phase E slack (G2 bar orders).
// ---------------------------------------------------------------------------
__global__ __launch_bounds__(TPB, 1) void qmamba_main(
    const float* __restrict__ angles,
    const float* __restrict__ poly,
    const float* __restrict__ cparams,
    const float* __restrict__ Dg,
    float* __restrict__ out)
{
  __shared__ u64 bufA[NST], bufB[NST];
  __shared__ float2 Ug[20][4];
  __shared__ u64 Ugp[20][2][4];      // packed shuffle coeffs (staging)
  __shared__ u64 Urp[8][8];          // packed reg coeffs {0,1,8,9,10,11,18,19}
  __shared__ float SLo[32], SHi[32]; // next-step psi tables (intra-step scratch)
  __shared__ float Alo[32], Ahi[32]; // current-step amplitude tables
  __shared__ float chs[NQ], shs[NQ], whsN[NQ], fcs[NQ], fss[NQ];
  __shared__ float pcs[4], Dsh[NQ];
  __shared__ float zred[8][NQ];

  const int tid = threadIdx.x;
  const int lane = tid & 31;
  const int warp = tid >> 5;
  const int b = blockIdx.x;

  // ---- setup ---------------------------------------------------------------
  if (tid < 20) {
    int layer = tid/10, wire = tid%10;
    int k = (layer*NQ + wire)*3;
    float al = cparams[k], be = cparams[k+1], ga = cparams[k+2];
    float sa, ca, sb, cb, sg, cg;
    sincosf(0.5f*al, &sa, &ca);
    sincosf(0.5f*be, &sb, &cb);
    sincosf(0.5f*ga, &sg, &cg);
    float2 m00 = make_float2( cb*ca,  sb*sa);
    float2 m01 = make_float2(-sb*ca, -cb*sa);
    float2 m10 = make_float2( sb*ca, -cb*sa);
    float2 m11 = make_float2( cb*ca, -sb*sa);
    float2 e0 = make_float2(cg, -sg);
    float2 e1 = make_float2(cg,  sg);
    Ug[tid][0] = cmul(e0, m00);
    Ug[tid][1] = cmul(e0, m01);
    Ug[tid][2] = cmul(e1, m10);
    Ug[tid][3] = cmul(e1, m11);
  }
  if (tid < 4) pcs[tid] = poly[tid];
  float pA = 0.f, pC = 0.f;
  if (tid < NQ) {
    Dsh[tid] = Dg[tid];
    int bi = b*SQ*NQ + tid;
    pA = angles[bi]; pC = g_C[bi];
    float dta = g_dta[bi];
    chs[tid] = 1.f; shs[tid] = 0.f;     // h=0 at step 0
    whsN[tid] = dta * (0.5f*PI_F);      // step-0 psi weights
    float s_, c_;
    __sincosf(0.5f*pA*dta, &s_, &c_);
    fcs[tid] = c_; fss[tid] = s_;
  }
  __syncthreads();

  // static packed shuffle-gate coefficients Ugp[g][bt][c] (staging)
  if (tid < 160) {
    int g = tid >> 3;
    int bt = (tid >> 2) & 1;
    int c = tid & 3;
    float2 cs = bt ? Ug[g][3] : Ug[g][0];
    float2 cp = bt ? Ug[g][2] : Ug[g][1];
    float val = (c==0) ? cs.x : (c==1) ? cs.y : (c==2) ? cp.x : cp.y;
    Ugp[g][bt][c] = pk2(val, val);
  }
  // static packed reg-gate coefficients for gates {0,1,8,9,10,11,18,19}
  if (tid < 64) {
    const int glist[8] = {0,1,8,9,10,11,18,19};
    int gi = tid >> 3;
    int c = (tid >> 1) & 3;
    int part = tid & 1;
    float2 gv = Ug[glist[gi]][c];
    float val = part ? gv.y : gv.x;
    Urp[gi][2*c+part] = pk2(val, val);
  }

  // per-thread static: QSVT gather powers + exchange index sets
  int rT1[AMPS], rT2[AMPS], rT3[AMPS], rT4[AMPS];
  int dstT[AMPS], dstG[AMPS];
#pragma unroll
  for (int m=0;m<AMPS;m++){
    int a = tid*AMPS + m;
    rT1[m] = gmap(a);
    rT2[m] = gmap(rT1[m]);
    rT3[m] = gmap(rT2[m]);
    rT4[m] = gmap(rT3[m]);
    int xp = bswap(a);
    int t1 = xp >> 2;
    dstT[m] = ((xp & 3) << 8) | (t1 ^ ((t1 >> 5) & 1));
    int xg = grayinv(xp);
    int tg = xg >> 2;
    dstG[m] = ((xg & 3) << 8) | (tg ^ ((tg >> 5) & 1));
  }
  const int ldb = tid ^ ((tid >> 5) & 1);   // own-slot swizzled load base
  __syncthreads();

  // ---- hoist complex shuffle-gate coefficients into registers --------------
  u64 CC[12][4];
  {
    const int gl[12] = {3,4,5,6,7, 2, 13,14,15,16,17, 12};
    const int qb[12] = {4,3,2,1,0, 0, 4,3,2,1,0, 0};
#pragma unroll
    for (int i=0;i<12;i++){
      int bt = (lane >> qb[i]) & 1;
#pragma unroll
      for (int c=0;c<4;c++) CC[i][c] = Ugp[gl[i]][bt][c];
    }
  }

  // ---- prologue: step-0 S/A tables + step-0 phase factors ------------------
  if (tid < 64) {
    int j = tid & 31;
    bool hi = tid >= 32;
    float sm = 0.f, am = 1.f;
#pragma unroll
    for (int q=0;q<5;q++){
      int w = hi ? (4-q) : (9-q);
      int bit = (j>>q)&1;
      sm += bit ? whsN[w] : -whsN[w];
      am *= bit ? shs[w] : chs[w];
    }
    if (hi){ SHi[j]=sm; Ahi[j]=am; } else { SLo[j]=sm; Alo[j]=am; }
  }
  __syncthreads();
  u64 vE[AMPS];
  {
    float p0=pcs[0], p1=pcs[1], p2=pcs[2], p3=pcs[3];
#pragma unroll
    for (int m=0;m<AMPS;m++){
      float phi = p3*(SHi[rT1[m]>>5] + SLo[rT1[m]&31])
                + p2*(SHi[rT2[m]>>5] + SLo[rT2[m]&31])
                + p1*(SHi[rT3[m]>>5] + SLo[rT3[m]&31])
                + p0*(SHi[rT4[m]>>5] + SLo[rT4[m]&31]);
      float sp, cp; __sincosf(phi, &sp, &cp);
      vE[m] = pk2(cp, sp);
    }
  }

  u64 v[AMPS];

  // ---- sequential scan -----------------------------------------------------
#pragma unroll 1
  for (int s = 0; s < SQ; ++s) {
    // prefetch next-step per-wire inputs; publish next psi weights
    float nA=0.f, nD=0.f, nC=0.f;
    if (tid < NQ && s+1 < SQ) {
      int bn = (b*SQ + s + 1)*NQ + tid;
      nA = angles[bn]; nD = g_dta[bn]; nC = g_C[bn];
      whsN[tid] = nD * (0.5f*PI_F);     // for next step's phase (T1 bar orders)
    }

    // init (short head): am from A tables x pipelined phase factor
#pragma unroll
    for (int m=0;m<AMPS;m++){
      float am = Ahi[rT4[m]>>5] * Alo[rT4[m]&31];
      v[m] = mul2d(pk2(am, am), vE[m]);
    }

    // ==== phase A (L0): layer-1 wires 3..7 (shfl), 8,9 (reg) ====
    shflCr(v, CC[0], 4);
    shflCr(v, CC[1], 3);
    shflCr(v, CC[2], 2);
    shflCr(v, CC[3], 1);
    shflCr(v, CC[4], 0);
    regCp(v, Urp[2], 2);   // gate 8
    regCp(v, Urp[3], 1);   // gate 9
    // T1: L0 -> L1
#pragma unroll
    for (int m=0;m<AMPS;m++) bufA[dstT[m]] = v[m];
    __syncthreads();
#pragma unroll
    for (int m=0;m<AMPS;m++) v[m] = bufA[(m<<8) | ldb];
    // ==== phase B (L1): layer-1 wires 0,1 (reg), 2 (lane0) ====
    regCp(v, Urp[0], 2);
    regCp(v, Urp[1], 1);
    shflCr(v, CC[5], 0);
    // G1: chain gather + back to L0
#pragma unroll
    for (int m=0;m<AMPS;m++) bufB[dstG[m]] = v[m];
    __syncthreads();
#pragma unroll
    for (int m=0;m<AMPS;m++) v[m] = bufB[(m<<8) | ldb];

    // ==== phase C (L0): layer-2 wires 3..7, 8,9 + S-table build in slack ====
    if (tid < 64) {
      int j = tid & 31;
      bool hi = tid >= 32;
      float sm = 0.f;
#pragma unroll
      for (int q=0;q<5;q++){
        int w = hi ? (4-q) : (9-q);
        sm += ((j>>q)&1) ? whsN[w] : -whsN[w];
      }
      if (hi) SHi[j]=sm; else SLo[j]=sm;
    }
    shflCr(v, CC[6], 4);
    shflCr(v, CC[7], 3);
    shflCr(v, CC[8], 2);
    shflCr(v, CC[9], 1);
    shflCr(v, CC[10], 0);
    regCp(v, Urp[6], 2);   // gate 18
    regCp(v, Urp[7], 1);   // gate 19
    // T2: L0 -> L1
#pragma unroll
    for (int m=0;m<AMPS;m++) bufA[dstT[m]] = v[m];
    __syncthreads();
#pragma unroll
    for (int m=0;m<AMPS;m++) v[m] = bufA[(m<<8) | ldb];
    // ==== phase D (L1): layer-2 wires 0,1,2 ====
    regCp(v, Urp[4], 2);
    regCp(v, Urp[5], 1);
    shflCr(v, CC[11], 0);
    // G2: chain gather + back to L0
#pragma unroll
    for (int m=0;m<AMPS;m++) bufB[dstG[m]] = v[m];
    __syncthreads();
#pragma unroll
    for (int m=0;m<AMPS;m++) v[m] = bufB[(m<<8) | ldb];

    // ==== phase E (L0): final RY wires 3..7, 8,9 + next phase factors =======
    {
      float p0=pcs[0], p1=pcs[1], p2=pcs[2], p3=pcs[3];
#pragma unroll
      for (int m=0;m<AMPS;m++){
        float phi = p3*(SHi[rT1[m]>>5] + SLo[rT1[m]&31])
                  + p2*(SHi[rT2[m]>>5] + SLo[rT2[m]&31])
                  + p1*(SHi[rT3[m]>>5] + SLo[rT3[m]&31])
                  + p0*(SHi[rT4[m]>>5] + SLo[rT4[m]&31]);
        float sp, cp; __sincosf(phi, &sp, &cp);
        vE[m] = pk2(cp, sp);
      }
    }
    shflRp(v, fcs[3], fss[3], 4, lane);
    shflRp(v, fcs[4], fss[4], 3, lane);
    shflRp(v, fcs[5], fss[5], 2, lane);
    shflRp(v, fcs[6], fss[6], 1, lane);
    shflRp(v, fcs[7], fss[7], 0, lane);
    regRp(v, fcs[8], fss[8], 2);
    regRp(v, fcs[9], fss[9], 1);
    // T3: L0 -> L1
#pragma unroll
    for (int m=0;m<AMPS;m++) bufA[dstT[m]] = v[m];
    __syncthreads();
#pragma unroll
    for (int m=0;m<AMPS;m++) v[m] = bufA[(m<<8) | ldb];
    // ==== phase F (L1): final RY wires 0,1,2 ====
    regRp(v, fcs[0], fss[0], 2);
    regRp(v, fcs[1], fss[1], 1);
    shflRp(v, fcs[2], fss[2], 0, lane);

    // ======== measurement (L1 layout) ========
    float S=0.f, SbH=0.f, SbL=0.f;
#pragma unroll
    for (int m=0;m<AMPS;m++){
      float2 f = up2(v[m]);
      float pm = f.x*f.x + f.y*f.y;
      S += pm;
      if (m & 2) SbH += pm;   // wire 0
      if (m & 1) SbL += pm;   // wire 1
    }
#pragma unroll
    for (int off=16; off>0; off>>=1){
      SbH += __shfl_xor_sync(0xffffffffu, SbH, off);
      SbL += __shfl_xor_sync(0xffffffffu, SbL, off);
    }
#pragma unroll
    for (int q=16; q>0; q>>=1){
      float t = __shfl_xor_sync(0xffffffffu, S, q);
      S = ((lane & q) ? (t - S) : (S + t));
    }
    if (lane == 0){
      zred[warp][8] = (warp&4) ? -S : S;
      zred[warp][9] = (warp&2) ? -S : S;
      zred[warp][7] = (warp&1) ? -S : S;
      zred[warp][0] = S - 2.f*SbH;
      zred[warp][1] = S - 2.f*SbL;
    } else if (lane == 16) zred[warp][3] = S;
    else if (lane == 8)  zred[warp][4] = S;
    else if (lane == 4)  zred[warp][5] = S;
    else if (lane == 2)  zred[warp][6] = S;
    else if (lane == 1)  zred[warp][2] = S;
    __syncthreads();

    // ======== tail: h update + next-step scalars + A tables ========
    if (tid < NQ){
      float hn = zred[0][tid] + zred[1][tid] + zred[2][tid] + zred[3][tid]
               + zred[4][tid] + zred[5][tid] + zred[6][tid] + zred[7][tid];
      int bi = (b*SQ + s)*NQ + tid;
      out[bi] = pC*hn + Dsh[tid]*pA;
      if (s+1 < SQ){
        float s_, c_;
        __sincosf(0.5f*hn, &s_, &c_);
        chs[tid] = c_; shs[tid] = s_;
        __sincosf(0.5f*nA*nD, &s_, &c_);
        fcs[tid] = c_; fss[tid] = s_;
        pA = nA; pC = nC;
      }
    }
    __syncthreads();
    if (tid < 64) {                     // A tables for next step
      int j = tid & 31;
      bool hi = tid >= 32;
      float am = 1.f;
#pragma unroll
      for (int q=0;q<5;q++){
        int w = hi ? (4-q) : (9-q);
        am *= ((j>>q)&1) ? shs[w] : chs[w];
      }
      if (hi) Ahi[j]=am; else Alo[j]=am;
    }
    __syncthreads();
  }
}

// ---------------------------------------------------------------------------
extern "C" void kernel_launch(void* const* d_in, const int* in_sizes, int n_in,
                              void* d_out, int out_size)
{
  const float* angles  = (const float*)d_in[0];
  const float* W_x     = (const float*)d_in[1];
  const float* W_dt    = (const float*)d_in[2];
  const float* b_dt    = (const float*)d_in[3];
  const float* poly    = (const float*)d_in[4];
  const float* cparams = (const float*)d_in[5];
  const float* D       = (const float*)d_in[6];
  float* out = (float*)d_out;

  prep_kernel<<<(BQ*SQ + 255)/256, 256>>>(angles, W_x, W_dt, b_dt);
  qmamba_main<<<BQ, TPB>>>(angles, poly, cparams, D, out);
}